// round 5
// baseline (speedup 1.0000x reference)
#include <cuda_runtime.h>
#include <cuda_bf16.h>
#include <cstdint>

#define DD 128
#define NMAX 50000
#define EMAX 640000

typedef uint32_t u32;

// ---------------- device scratch ----------------
__device__ __align__(16) float g_Hq[NMAX * DD];
__device__ __align__(16) float g_Hr[NMAX * DD];
__device__ __align__(16) float g_Vh[NMAX * DD];
__device__ __align__(16) float g_Hu[NMAX * DD];
__device__ __align__(16) float g_agg[NMAX * DD];
__device__ __align__(16) float g_ehat[(size_t)EMAX * DD];
__device__ __align__(16) float g_stats[4 * DD];  // sum_e, ssq_e, sum_n, ssq_n
// weights [P,Q,R,V,U,W1,W2] x {hi,lo}: W^T (row=n, col=k), bf16, chunk-XOR swizzled
__device__ __align__(16) __nv_bfloat16 g_wb[7][2][DD * DD];

// ---------------- helpers ----------------
__device__ __forceinline__ u32 smem_u32(const void* p) {
    u32 a;
    asm("{ .reg .u64 t; cvta.to.shared.u64 t, %1; cvt.u32.u64 %0, t; }" : "=r"(a) : "l"(p));
    return a;
}
// byte offset in a [128 rows x 128 cols] bf16 tile, 256B rows, 16B-chunk XOR swizzle
__device__ __forceinline__ int swoff(int row, int col) {
    return (row << 8) + ((((col >> 3) ^ (row & 7)) << 4)) + ((col & 7) << 1);
}
__device__ __forceinline__ void ldsm4(u32& r0, u32& r1, u32& r2, u32& r3, u32 a) {
    asm volatile("ldmatrix.sync.aligned.m8n8.x4.shared.b16 {%0,%1,%2,%3}, [%4];"
                 : "=r"(r0), "=r"(r1), "=r"(r2), "=r"(r3) : "r"(a));
}
__device__ __forceinline__ void mma_bf16(float c[4], u32 a0, u32 a1, u32 a2, u32 a3,
                                         u32 b0, u32 b1) {
    asm volatile(
        "mma.sync.aligned.m16n8k16.row.col.f32.bf16.bf16.f32 "
        "{%0,%1,%2,%3},{%4,%5,%6,%7},{%8,%9},{%0,%1,%2,%3};"
        : "+f"(c[0]), "+f"(c[1]), "+f"(c[2]), "+f"(c[3])
        : "r"(a0), "r"(a1), "r"(a2), "r"(a3), "r"(b0), "r"(b1));
}
__device__ __forceinline__ float sigm(float x) { return 1.0f / (1.0f + __expf(-x)); }
__device__ __forceinline__ void red2(float* p, float a, float b) {
    asm volatile("red.global.add.v2.f32 [%0], {%1,%2};" :: "l"(p), "f"(a), "f"(b) : "memory");
}

// split-GEMM core: acc += Ahi*Bhi + Ahi*Blo + Alo*Bhi for this warp's 16-row block
__device__ __forceinline__ void hmma_split(u32 aHi, u32 aLo, u32 bHi, u32 bLo,
                                           int wid, int lid, float acc[16][4]) {
    const int arow = wid * 16 + (lid & 7) + ((lid >> 3) & 1) * 8;
    const int akc1 = (lid >> 4) & 1;
    const int bro  = ((lid >> 4) & 1) * 8 + (lid & 7);
    const int bkc1 = (lid >> 3) & 1;
#pragma unroll
    for (int k = 0; k < 8; ++k) {
        const int akc = 2 * k + akc1;
        const u32 aoff = (u32)((arow << 8) + (((akc ^ (arow & 7)) << 4)));
        u32 ah0, ah1, ah2, ah3, al0, al1, al2, al3;
        ldsm4(ah0, ah1, ah2, ah3, aHi + aoff);
        ldsm4(al0, al1, al2, al3, aLo + aoff);
#pragma unroll
        for (int np = 0; np < 8; ++np) {
            const int brow = np * 16 + bro;
            const int bkc = 2 * k + bkc1;
            const u32 boff = (u32)((brow << 8) + ((bkc ^ (brow & 7)) << 4));
            u32 bh0, bh1, bh2, bh3, bl0, bl1, bl2, bl3;
            ldsm4(bh0, bh1, bh2, bh3, bHi + boff);
            ldsm4(bl0, bl1, bl2, bl3, bLo + boff);
            mma_bf16(acc[2 * np],     ah0, ah1, ah2, ah3, bh0, bh1);
            mma_bf16(acc[2 * np],     ah0, ah1, ah2, ah3, bl0, bl1);
            mma_bf16(acc[2 * np],     al0, al1, al2, al3, bh0, bh1);
            mma_bf16(acc[2 * np + 1], ah0, ah1, ah2, ah3, bh2, bh3);
            mma_bf16(acc[2 * np + 1], ah0, ah1, ah2, ah3, bl2, bl3);
            mma_bf16(acc[2 * np + 1], al0, al1, al2, al3, bh2, bh3);
        }
    }
}

__device__ __forceinline__ void zacc(float acc[16][4]) {
#pragma unroll
    for (int n = 0; n < 16; ++n) {
        acc[n][0] = 0.f; acc[n][1] = 0.f; acc[n][2] = 0.f; acc[n][3] = 0.f;
    }
}

// convert 8 fp32 -> bf16 hi/lo, store 16B each at swizzled (row, col..col+7)
__device__ __forceinline__ void conv8(char* Ahi, char* Alo, int row, int col, const float* f) {
    __align__(16) __nv_bfloat162 hv[4], lv[4];
#pragma unroll
    for (int j = 0; j < 4; ++j) {
        __nv_bfloat162 hh = __floats2bfloat162_rn(f[2 * j], f[2 * j + 1]);
        hv[j] = hh;
        lv[j] = __floats2bfloat162_rn(f[2 * j] - __bfloat162float(hh.x),
                                      f[2 * j + 1] - __bfloat162float(hh.y));
    }
    const int o = swoff(row, col);
    *(uint4*)(Ahi + o) = *(uint4*)hv;
    *(uint4*)(Alo + o) = *(uint4*)lv;
}

// load 128-row fp32 tile -> A hi/lo smem; optional BN scale/shift fused
__device__ __forceinline__ void load_A(const float* __restrict__ src, long long r0,
                                       long long nrows, char* Ahi, char* Alo, int tid,
                                       const float* sc, const float* sh) {
    const int row = tid >> 1;
    const int cb = (tid & 1) * 64;
    const long long grow = r0 + row;
    float f[8];
    if (grow < nrows) {
        const float4* gp = (const float4*)(src + grow * DD + cb);
#pragma unroll
        for (int g = 0; g < 8; ++g) {
            float4 u = gp[2 * g], v = gp[2 * g + 1];
            f[0] = u.x; f[1] = u.y; f[2] = u.z; f[3] = u.w;
            f[4] = v.x; f[5] = v.y; f[6] = v.z; f[7] = v.w;
            if (sc) {
                const int c = cb + 8 * g;
#pragma unroll
                for (int j = 0; j < 8; ++j) f[j] = fmaf(f[j], sc[c + j], sh[c + j]);
            }
            conv8(Ahi, Alo, row, cb + 8 * g, f);
        }
    } else {
#pragma unroll
        for (int j = 0; j < 8; ++j) f[j] = 0.f;
#pragma unroll
        for (int g = 0; g < 8; ++g) conv8(Ahi, Alo, row, cb + 8 * g, f);
    }
}

// copy a prepped (already swizzled) weight into B smem
__device__ __forceinline__ void load_B(int widx, char* Bhi, char* Blo, int tid) {
    const uint4* gh = (const uint4*)&g_wb[widx][0][0];
    const uint4* gl = (const uint4*)&g_wb[widx][1][0];
    uint4* dh = (uint4*)Bhi;
    uint4* dl = (uint4*)Blo;
#pragma unroll 4
    for (int i = tid; i < 2048; i += 256) { dh[i] = gh[i]; dl[i] = gl[i]; }
}

// ---------------- prep: W^T hi/lo swizzled; zero stats ----------------
__global__ void k_prep(const float* __restrict__ P, const float* __restrict__ Q,
                       const float* __restrict__ R, const float* __restrict__ V,
                       const float* __restrict__ U, const float* __restrict__ W1,
                       const float* __restrict__ W2) {
    const int w = blockIdx.x;
    const int tid = threadIdx.x;
    const float* Ws[7] = {P, Q, R, V, U, W1, W2};
    const float* W = Ws[w];
    if (w == 0) { g_stats[tid] = 0.f; g_stats[tid + 256] = 0.f; }
    char* bh = (char*)&g_wb[w][0][0];
    char* bl = (char*)&g_wb[w][1][0];
    for (int p = tid; p < DD * DD / 2; p += 256) {
        const int n = p >> 6;
        const int k2 = (p & 63) * 2;
        const float x0 = W[k2 * DD + n];
        const float x1 = W[(k2 + 1) * DD + n];
        __nv_bfloat162 hh = __floats2bfloat162_rn(x0, x1);
        __nv_bfloat162 ll = __floats2bfloat162_rn(x0 - __bfloat162float(hh.x),
                                                  x1 - __bfloat162float(hh.y));
        const int o = swoff(n, k2);
        *(u32*)(bh + o) = *(u32*)&hh;
        *(u32*)(bl + o) = *(u32*)&ll;
    }
}

// ---------------- node GEMMs: Hq/Hr/Vh/Hu = h @ {Q,R,V,U} ----------------
__global__ void __launch_bounds__(256, 1)
k_node(const float* __restrict__ h, int N) {
    extern __shared__ char sm[];
    char* Ahi = sm;          char* Alo = sm + 32768;
    char* Bhi = sm + 65536;  char* Blo = sm + 98304;
    const int tid = threadIdx.x, wid = tid >> 5, lid = tid & 31;
    const long long n0 = (long long)blockIdx.x * DD;

    load_A(h, n0, N, Ahi, Alo, tid, 0, 0);
    const u32 aHi = smem_u32(Ahi), aLo = smem_u32(Alo);
    const u32 bHi = smem_u32(Bhi), bLo = smem_u32(Blo);
    float* Outs[4] = {g_Hq, g_Hr, g_Vh, g_Hu};
    const int lr = wid * 16 + (lid >> 2);
    const int q2 = (lid & 3) * 2;

#pragma unroll 1
    for (int w = 0; w < 4; ++w) {
        load_B(1 + w, Bhi, Blo, tid);
        __syncthreads();
        float acc[16][4];
        zacc(acc);
        hmma_split(aHi, aLo, bHi, bLo, wid, lid, acc);
        const long long r0 = n0 + lr, r1 = r0 + 8;
        float* Out = Outs[w];
#pragma unroll
        for (int n = 0; n < 16; ++n) {
            const int col = n * 8 + q2;
            if (r0 < N) *(float2*)(Out + (size_t)r0 * DD + col) = make_float2(acc[n][0], acc[n][1]);
            if (r1 < N) *(float2*)(Out + (size_t)r1 * DD + col) = make_float2(acc[n][2], acc[n][3]);
        }
        __syncthreads();
    }
}

// ---- edge: ehat = e@P + Hq[src] + Hr[dst]; gate scatter; BN-e stats --------
__global__ void __launch_bounds__(256, 1)
k_ehat(const float* __restrict__ e, const int* __restrict__ src,
       const int* __restrict__ dst, int E) {
    extern __shared__ char sm[];
    char* Ahi = sm;          char* Alo = sm + 32768;
    char* Bhi = sm + 65536;  char* Blo = sm + 98304;
    __shared__ int s_src[DD], s_dst[DD];
    __shared__ float s_sum[DD], s_ssq[DD];
    const int tid = threadIdx.x, wid = tid >> 5, lid = tid & 31;
    const long long e0 = (long long)blockIdx.x * DD;

    load_A(e, e0, E, Ahi, Alo, tid, 0, 0);
    load_B(0, Bhi, Blo, tid);
    if (tid < DD) {
        const long long row = e0 + tid;
        s_src[tid] = (row < E) ? src[row] : 0;
        s_dst[tid] = (row < E) ? dst[row] : 0;
        s_sum[tid] = 0.f;
        s_ssq[tid] = 0.f;
    }
    __syncthreads();

    float acc[16][4];
    zacc(acc);
    hmma_split(smem_u32(Ahi), smem_u32(Alo), smem_u32(Bhi), smem_u32(Blo), wid, lid, acc);

    const int lr0 = wid * 16 + (lid >> 2), lr1 = lr0 + 8;
    const int q2 = (lid & 3) * 2;
    const long long r0 = e0 + lr0, r1 = e0 + lr1;
    const int sv0 = s_src[lr0], dv0 = s_dst[lr0];
    const int sv1 = s_src[lr1], dv1 = s_dst[lr1];
    const bool ok0 = r0 < E, ok1 = r1 < E;
#pragma unroll
    for (int n = 0; n < 16; ++n) {
        const int col = n * 8 + q2;
        float ls0 = 0.f, ls1 = 0.f, lq0 = 0.f, lq1 = 0.f;
        if (ok0) {
            float2 hq = *(const float2*)(g_Hq + (size_t)sv0 * DD + col);
            float2 hr = *(const float2*)(g_Hr + (size_t)dv0 * DD + col);
            float2 vh = *(const float2*)(g_Vh + (size_t)dv0 * DD + col);
            const float v0 = acc[n][0] + hq.x + hr.x;
            const float v1 = acc[n][1] + hq.y + hr.y;
            *(float2*)(g_ehat + (size_t)r0 * DD + col) = make_float2(v0, v1);
            red2(g_agg + (size_t)sv0 * DD + col, sigm(v0) * vh.x, sigm(v1) * vh.y);
            ls0 += v0; ls1 += v1; lq0 += v0 * v0; lq1 += v1 * v1;
        }
        if (ok1) {
            float2 hq = *(const float2*)(g_Hq + (size_t)sv1 * DD + col);
            float2 hr = *(const float2*)(g_Hr + (size_t)dv1 * DD + col);
            float2 vh = *(const float2*)(g_Vh + (size_t)dv1 * DD + col);
            const float v2 = acc[n][2] + hq.x + hr.x;
            const float v3 = acc[n][3] + hq.y + hr.y;
            *(float2*)(g_ehat + (size_t)r1 * DD + col) = make_float2(v2, v3);
            red2(g_agg + (size_t)sv1 * DD + col, sigm(v2) * vh.x, sigm(v3) * vh.y);
            ls0 += v2; ls1 += v3; lq0 += v2 * v2; lq1 += v3 * v3;
        }
        atomicAdd(&s_sum[col], ls0);
        atomicAdd(&s_sum[col + 1], ls1);
        atomicAdd(&s_ssq[col], lq0);
        atomicAdd(&s_ssq[col + 1], lq1);
    }
    __syncthreads();
    if (tid < DD) {
        atomicAdd(&g_stats[tid], s_sum[tid]);
        atomicAdd(&g_stats[DD + tid], s_ssq[tid]);
    }
}

// ---- edge MLP: e_new = e + relu(BN(ehat)@W1+b1)@W2 + b2 --------------------
__global__ void __launch_bounds__(256, 1)
k_mlp(const float* __restrict__ e, const float* __restrict__ b1,
      const float* __restrict__ b2, const float* __restrict__ ge,
      const float* __restrict__ be, float* __restrict__ out_e, int E) {
    extern __shared__ char sm[];
    char* Ahi = sm;          char* Alo = sm + 32768;
    char* Bhi = sm + 65536;  char* Blo = sm + 98304;
    __shared__ float s_sc[DD], s_sh[DD];
    const int tid = threadIdx.x, wid = tid >> 5, lid = tid & 31;
    const long long e0 = (long long)blockIdx.x * DD;

    if (tid < DD) {
        const float inv = 1.0f / (float)E;
        const float mean = g_stats[tid] * inv;
        const float var = g_stats[DD + tid] * inv - mean * mean;
        const float sc = ge[tid] * rsqrtf(var + 1e-5f);
        s_sc[tid] = sc;
        s_sh[tid] = be[tid] - mean * sc;
    }
    load_B(5, Bhi, Blo, tid);  // W1
    __syncthreads();           // s_sc/s_sh ready
    load_A(g_ehat, e0, E, Ahi, Alo, tid, s_sc, s_sh);
    __syncthreads();

    float acc[16][4];
    zacc(acc);
    hmma_split(smem_u32(Ahi), smem_u32(Alo), smem_u32(Bhi), smem_u32(Blo), wid, lid, acc);

    // hidden = relu(acc + b1) -> overwrite own A rows (hi/lo, swizzled 4B stores)
    const int lr0 = wid * 16 + (lid >> 2), lr1 = lr0 + 8;
    const int q2 = (lid & 3) * 2;
#pragma unroll
    for (int n = 0; n < 16; ++n) {
        const int col = n * 8 + q2;
        const float2 bb = *(const float2*)(b1 + col);
        const float v0 = fmaxf(acc[n][0] + bb.x, 0.f), v1 = fmaxf(acc[n][1] + bb.y, 0.f);
        const float v2 = fmaxf(acc[n][2] + bb.x, 0.f), v3 = fmaxf(acc[n][3] + bb.y, 0.f);
        __nv_bfloat162 h0 = __floats2bfloat162_rn(v0, v1);
        __nv_bfloat162 l0 = __floats2bfloat162_rn(v0 - __bfloat162float(h0.x),
                                                  v1 - __bfloat162float(h0.y));
        __nv_bfloat162 h1 = __floats2bfloat162_rn(v2, v3);
        __nv_bfloat162 l1 = __floats2bfloat162_rn(v2 - __bfloat162float(h1.x),
                                                  v3 - __bfloat162float(h1.y));
        const int o0 = swoff(lr0, col), o1 = swoff(lr1, col);
        *(u32*)(Ahi + o0) = *(u32*)&h0;
        *(u32*)(Alo + o0) = *(u32*)&l0;
        *(u32*)(Ahi + o1) = *(u32*)&h1;
        *(u32*)(Alo + o1) = *(u32*)&l1;
    }
    __syncwarp();
    __syncthreads();           // all GEMM1 B-reads done
    load_B(6, Bhi, Blo, tid);  // W2
    __syncthreads();

    zacc(acc);
    hmma_split(smem_u32(Ahi), smem_u32(Alo), smem_u32(Bhi), smem_u32(Blo), wid, lid, acc);

    const long long r0 = e0 + lr0, r1 = e0 + lr1;
#pragma unroll
    for (int n = 0; n < 16; ++n) {
        const int col = n * 8 + q2;
        const float2 bb = *(const float2*)(b2 + col);
        if (r0 < E) {
            const float2 ev = *(const float2*)(e + (size_t)r0 * DD + col);
            *(float2*)(out_e + (size_t)r0 * DD + col) =
                make_float2(acc[n][0] + bb.x + ev.x, acc[n][1] + bb.y + ev.y);
        }
        if (r1 < E) {
            const float2 ev = *(const float2*)(e + (size_t)r1 * DD + col);
            *(float2*)(out_e + (size_t)r1 * DD + col) =
                make_float2(acc[n][2] + bb.x + ev.x, acc[n][3] + bb.y + ev.y);
        }
    }
}

// ---------------- node BN stats over x = Hu + agg ----------------
__global__ void k_nstats(int N) {
    const int tid = threadIdx.x;
    const int c = tid & 127, hh = tid >> 7;
    const int rbase = blockIdx.x * DD + hh * 64;
    float s = 0.f, q = 0.f;
    for (int i = 0; i < 64; ++i) {
        const int r = rbase + i;
        if (r < N) {
            const float x = g_Hu[(size_t)r * DD + c] + g_agg[(size_t)r * DD + c];
            s += x;
            q += x * x;
        }
    }
    atomicAdd(&g_stats[2 * DD + c], s);
    atomicAdd(&g_stats[3 * DD + c], q);
}

// ---------------- node finalize ----------------
__global__ void k_nfinal(const float* __restrict__ h, const float* __restrict__ gn,
                         const float* __restrict__ bnb, const float* __restrict__ alpha,
                         float* __restrict__ out, int N) {
    const size_t i = (size_t)blockIdx.x * blockDim.x + threadIdx.x;
    const size_t total = (size_t)N * (DD / 4);
    if (i >= total) return;
    const int c4 = (int)(i & 31);
    const float inv = 1.0f / (float)N;
    const float4 sum = ((const float4*)(g_stats + 2 * DD))[c4];
    const float4 ssq = ((const float4*)(g_stats + 3 * DD))[c4];
    const float4 gnv = ((const float4*)gn)[c4];
    const float4 bnv = ((const float4*)bnb)[c4];
    const float m0 = sum.x * inv, m1 = sum.y * inv, m2 = sum.z * inv, m3 = sum.w * inv;
    const float sc0 = gnv.x * rsqrtf(ssq.x * inv - m0 * m0 + 1e-5f);
    const float sc1 = gnv.y * rsqrtf(ssq.y * inv - m1 * m1 + 1e-5f);
    const float sc2 = gnv.z * rsqrtf(ssq.z * inv - m2 * m2 + 1e-5f);
    const float sc3 = gnv.w * rsqrtf(ssq.w * inv - m3 * m3 + 1e-5f);
    const float sh0 = bnv.x - m0 * sc0, sh1 = bnv.y - m1 * sc1;
    const float sh2 = bnv.z - m2 * sc2, sh3 = bnv.w - m3 * sc3;
    const float4 xu = ((const float4*)g_Hu)[i];
    const float4 ag = ((const float4*)g_agg)[i];
    const float4 hv = ((const float4*)h)[i];
    const float a = *alpha;
    float4 o;
    o.x = hv.x + a * fmaf(xu.x + ag.x, sc0, sh0);
    o.y = hv.y + a * fmaf(xu.y + ag.y, sc1, sh1);
    o.z = hv.z + a * fmaf(xu.z + ag.z, sc2, sh2);
    o.w = hv.w + a * fmaf(xu.w + ag.w, sc3, sh3);
    ((float4*)out)[i] = o;
}

extern "C" void kernel_launch(void* const* d_in, const int* in_sizes, int n_in,
                              void* d_out, int out_size) {
    const float* h   = (const float*)d_in[0];
    const float* e   = (const float*)d_in[1];
    const int*   ei  = (const int*)d_in[2];
    const float* Pw  = (const float*)d_in[3];
    const float* Qw  = (const float*)d_in[4];
    const float* Rw  = (const float*)d_in[5];
    const float* Uw  = (const float*)d_in[6];
    const float* Vw  = (const float*)d_in[7];
    const float* W1  = (const float*)d_in[8];
    const float* b1  = (const float*)d_in[9];
    const float* W2  = (const float*)d_in[10];
    const float* b2  = (const float*)d_in[11];
    const float* ge  = (const float*)d_in[12];
    const float* be  = (const float*)d_in[13];
    const float* gn  = (const float*)d_in[14];
    const float* bnb = (const float*)d_in[15];
    const float* alpha = (const float*)d_in[16];

    const int N = in_sizes[0] / DD;
    const int E = in_sizes[1] / DD;
    const int* src = ei;
    const int* dst = ei + E;

    float* out_h = (float*)d_out;
    float* out_e = out_h + (size_t)N * DD;

    const int SMEM = 131072;
    cudaFuncSetAttribute(k_node, cudaFuncAttributeMaxDynamicSharedMemorySize, SMEM);
    cudaFuncSetAttribute(k_ehat, cudaFuncAttributeMaxDynamicSharedMemorySize, SMEM);
    cudaFuncSetAttribute(k_mlp,  cudaFuncAttributeMaxDynamicSharedMemorySize, SMEM);

    void* agg_ptr;
    cudaGetSymbolAddress(&agg_ptr, g_agg);
    cudaMemsetAsync(agg_ptr, 0, (size_t)N * DD * sizeof(float), 0);

    const int nb  = (N + DD - 1) / DD;
    const int ebt = (E + DD - 1) / DD;

    // order: memset(0), prep(1), node(2), ehat(3), mlp(4), nstats(5), nfinal(6)
    // -> ncu (-s 5, observed to capture launch index 4) profiles k_mlp
    k_prep<<<7, 256>>>(Pw, Qw, Rw, Vw, Uw, W1, W2);
    k_node<<<nb, 256, SMEM>>>(h, N);
    k_ehat<<<ebt, 256, SMEM>>>(e, src, dst, E);
    k_mlp<<<ebt, 256, SMEM>>>(e, b1, b2, ge, be, out_e, E);
    k_nstats<<<nb, 256>>>(N);
    k_nfinal<<<(int)(((size_t)N * 32 + 255) / 256), 256>>>(h, gn, bnb, alpha, out_h, N);
}

// round 6
// speedup vs baseline: 1.4746x; 1.4746x over previous
#include <cuda_runtime.h>
#include <cuda_bf16.h>
#include <cstdint>

#define DD 128
#define NMAX 50000
#define EMAX 640000
typedef uint32_t u32;

// ---------------- device scratch ----------------
__device__ __align__(16) float g_Hq[NMAX * DD];
__device__ __align__(16) float g_Hr[NMAX * DD];
__device__ __align__(16) float g_Vh[NMAX * DD];
__device__ __align__(16) float g_Hu[NMAX * DD];
__device__ __align__(16) float g_agg[NMAX * DD];
__device__ __align__(16) float g_ehat[(size_t)EMAX * DD];
__device__ __align__(16) float g_stats[4 * DD];
// B weight fragments, ready for mma: [w][prec][ks][lane][j*2+r] (u32 = bf16x2)
__device__ __align__(16) u32 g_wf[7 * 2 * 8 * 32 * 32];

// ---------------- helpers ----------------
__device__ __forceinline__ u32 smem_u32(const void* p) {
    u32 a;
    asm("{ .reg .u64 t; cvta.to.shared.u64 t, %1; cvt.u32.u64 %0, t; }" : "=r"(a) : "l"(p));
    return a;
}
__device__ __forceinline__ int swoff(int row, int col) {  // bf16 tile 128x128, 256B rows
    return (row << 8) + ((((col >> 3) ^ (row & 7)) << 4)) + ((col & 7) << 1);
}
__device__ __forceinline__ void ldsm4(u32 r[4], u32 a) {
    asm volatile("ldmatrix.sync.aligned.m8n8.x4.shared.b16 {%0,%1,%2,%3}, [%4];"
                 : "=r"(r[0]), "=r"(r[1]), "=r"(r[2]), "=r"(r[3]) : "r"(a));
}
__device__ __forceinline__ void mma_bf16(float c[4], const u32 a[4], u32 b0, u32 b1) {
    asm volatile(
        "mma.sync.aligned.m16n8k16.row.col.f32.bf16.bf16.f32 "
        "{%0,%1,%2,%3},{%4,%5,%6,%7},{%8,%9},{%0,%1,%2,%3};"
        : "+f"(c[0]), "+f"(c[1]), "+f"(c[2]), "+f"(c[3])
        : "r"(a[0]), "r"(a[1]), "r"(a[2]), "r"(a[3]), "r"(b0), "r"(b1));
}
__device__ __forceinline__ float sigm(float x) { return 1.0f / (1.0f + __expf(-x)); }
__device__ __forceinline__ void red4(float* p, float a, float b, float c, float d) {
    asm volatile("red.global.add.v4.f32 [%0], {%1,%2,%3,%4};"
                 :: "l"(p), "f"(a), "f"(b), "f"(c), "f"(d) : "memory");
}

// GEMM core: CTA tile 128x128, warp tile 32x64 (rg=wid>>1 row-group, ch=wid&1 col-half).
// A: bf16 hi/lo in smem (swizzled); B: fragment vectors from g_wf (L1-resident).
// 3-pass split: AhBh + AhBl + AlBh, fp32 accum.
__device__ __forceinline__ void gemm_core(u32 aHi, u32 aLo, int w, int rg, int ch,
                                          int lid, float acc[2][8][4]) {
#pragma unroll
    for (int rb = 0; rb < 2; ++rb)
#pragma unroll
        for (int nt = 0; nt < 8; ++nt) {
            acc[rb][nt][0] = 0.f; acc[rb][nt][1] = 0.f;
            acc[rb][nt][2] = 0.f; acc[rb][nt][3] = 0.f;
        }
    const int ar0 = rg * 32 + (lid & 7) + ((lid >> 3) & 1) * 8;
    const int kc1 = (lid >> 4) & 1;
    const u32 whbase = (((u32)(w * 2) * 8) * 32 + (u32)lid) * 32 + (u32)ch * 16;
    const u32 wlbase = (((u32)(w * 2 + 1) * 8) * 32 + (u32)lid) * 32 + (u32)ch * 16;
#pragma unroll
    for (int ks = 0; ks < 8; ++ks) {
        const int akc = 2 * ks + kc1;
        const u32 ao0 = (u32)((ar0 << 8) + ((akc ^ (ar0 & 7)) << 4));
        const int ar1 = ar0 + 16;
        const u32 ao1 = (u32)((ar1 << 8) + ((akc ^ (ar1 & 7)) << 4));
        u32 ah[2][4], al[2][4];
        ldsm4(ah[0], aHi + ao0);
        ldsm4(ah[1], aHi + ao1);
        ldsm4(al[0], aLo + ao0);
        ldsm4(al[1], aLo + ao1);
        const uint4* ph = (const uint4*)(g_wf + whbase + (u32)ks * 1024);
        const uint4* pl = (const uint4*)(g_wf + wlbase + (u32)ks * 1024);
#pragma unroll
        for (int jp = 0; jp < 2; ++jp) {
            uint4 h0 = ph[jp * 2], h1 = ph[jp * 2 + 1];
            uint4 l0 = pl[jp * 2], l1 = pl[jp * 2 + 1];
            u32 bh[8] = {h0.x, h0.y, h0.z, h0.w, h1.x, h1.y, h1.z, h1.w};
            u32 bl[8] = {l0.x, l0.y, l0.z, l0.w, l1.x, l1.y, l1.z, l1.w};
#pragma unroll
            for (int t = 0; t < 4; ++t) {
                const int nt = jp * 4 + t;
#pragma unroll
                for (int rb = 0; rb < 2; ++rb) {
                    mma_bf16(acc[rb][nt], ah[rb], bh[2 * t], bh[2 * t + 1]);
                    mma_bf16(acc[rb][nt], ah[rb], bl[2 * t], bl[2 * t + 1]);
                    mma_bf16(acc[rb][nt], al[rb], bh[2 * t], bh[2 * t + 1]);
                }
            }
        }
    }
}

// fp32 -> bf16 hi/lo convert of 8 values, swizzled 16B stores
__device__ __forceinline__ void conv8(char* Ahi, char* Alo, int row, int col, const float* f) {
    __align__(16) __nv_bfloat162 hv[4], lv[4];
#pragma unroll
    for (int j = 0; j < 4; ++j) {
        __nv_bfloat162 hh = __floats2bfloat162_rn(f[2 * j], f[2 * j + 1]);
        hv[j] = hh;
        lv[j] = __floats2bfloat162_rn(f[2 * j] - __bfloat162float(hh.x),
                                      f[2 * j + 1] - __bfloat162float(hh.y));
    }
    const int o = swoff(row, col);
    *(uint4*)(Ahi + o) = *(uint4*)hv;
    *(uint4*)(Alo + o) = *(uint4*)lv;
}

__device__ __forceinline__ void load_A(const float* __restrict__ src, long long r0,
                                       long long nrows, char* Ahi, char* Alo, int tid,
                                       const float* sc, const float* sh) {
    const int row = tid >> 1;
    const int cb = (tid & 1) * 64;
    const long long grow = r0 + row;
    float f[8];
    if (grow < nrows) {
        const float4* gp = (const float4*)(src + grow * DD + cb);
#pragma unroll
        for (int g = 0; g < 8; ++g) {
            float4 u = gp[2 * g], v = gp[2 * g + 1];
            f[0] = u.x; f[1] = u.y; f[2] = u.z; f[3] = u.w;
            f[4] = v.x; f[5] = v.y; f[6] = v.z; f[7] = v.w;
            if (sc) {
                const int c = cb + 8 * g;
#pragma unroll
                for (int j = 0; j < 8; ++j) f[j] = fmaf(f[j], sc[c + j], sh[c + j]);
            }
            conv8(Ahi, Alo, row, cb + 8 * g, f);
        }
    } else {
#pragma unroll
        for (int j = 0; j < 8; ++j) f[j] = 0.f;
#pragma unroll
        for (int g = 0; g < 8; ++g) conv8(Ahi, Alo, row, cb + 8 * g, f);
    }
}

// ---------------- prep: weights -> fragment vectors; zero stats -------------
__global__ void k_prep(const float* __restrict__ P, const float* __restrict__ Q,
                       const float* __restrict__ R, const float* __restrict__ V,
                       const float* __restrict__ U, const float* __restrict__ W1,
                       const float* __restrict__ W2) {
    const int w = blockIdx.x;
    const int tid = threadIdx.x;
    const float* Ws[7] = {P, Q, R, V, U, W1, W2};
    const float* W = Ws[w];
    if (w == 0) { g_stats[tid] = 0.f; g_stats[tid + 256] = 0.f; }
    for (int idx = tid; idx < 8192; idx += 256) {
        const int r = idx & 1;
        const int j = (idx >> 1) & 15;
        const int lane = (idx >> 5) & 31;
        const int ks = idx >> 10;
        const int n = j * 8 + (lane >> 2);
        const int k = ks * 16 + (lane & 3) * 2 + r * 8;
        const float x0 = W[k * DD + n];
        const float x1 = W[(k + 1) * DD + n];
        __nv_bfloat162 hh = __floats2bfloat162_rn(x0, x1);
        __nv_bfloat162 ll = __floats2bfloat162_rn(x0 - __bfloat162float(hh.x),
                                                  x1 - __bfloat162float(hh.y));
        const u32 o = (((u32)(w * 2) * 8 + ks) * 32 + lane) * 32 + j * 2 + r;
        g_wf[o] = *(u32*)&hh;
        g_wf[o + 8192] = *(u32*)&ll;
    }
}

// ---------------- node GEMMs: two weights per launch -------------------------
__global__ void __launch_bounds__(256, 2)
k_node(const float* __restrict__ h, int N, int w0) {
    extern __shared__ char sm[];
    char* Ahi = sm;
    char* Alo = sm + 32768;
    const int tid = threadIdx.x, wid = tid >> 5, lid = tid & 31;
    const int rg = wid >> 1, ch = wid & 1;
    const long long n0 = (long long)blockIdx.x * DD;

    load_A(h, n0, N, Ahi, Alo, tid, 0, 0);
    __syncthreads();
    const u32 aHi = smem_u32(Ahi), aLo = smem_u32(Alo);

    float* Outs[5] = {0, g_Hq, g_Hr, g_Vh, g_Hu};
#pragma unroll 1
    for (int w = w0; w < w0 + 2; ++w) {
        float acc[2][8][4];
        gemm_core(aHi, aLo, w, rg, ch, lid, acc);
        float* Out = Outs[w];
#pragma unroll
        for (int rb = 0; rb < 2; ++rb) {
            const long long r0 = n0 + rg * 32 + rb * 16 + (lid >> 2);
            const long long r1 = r0 + 8;
#pragma unroll
            for (int nt = 0; nt < 8; ++nt) {
                const int col = ch * 64 + nt * 8 + (lid & 3) * 2;
                if (r0 < N) *(float2*)(Out + (size_t)r0 * DD + col) =
                    make_float2(acc[rb][nt][0], acc[rb][nt][1]);
                if (r1 < N) *(float2*)(Out + (size_t)r1 * DD + col) =
                    make_float2(acc[rb][nt][2], acc[rb][nt][3]);
            }
        }
    }
}

// ---- edge: ehat = e@P + Hq[src]+Hr[dst]; gate scatter; BN-e stats ----------
#define BUPITCH 132
__global__ void __launch_bounds__(256, 2)
k_ehat(const float* __restrict__ e, const int* __restrict__ src,
       const int* __restrict__ dst, int E) {
    extern __shared__ char sm[];
    char* Ahi = sm;
    char* Alo = sm + 32768;
    float* Bu = (float*)sm;  // fp32 128 x 132 (reuses A after GEMM)
    __shared__ int s_src[DD], s_dst[DD];
    __shared__ float s_sum[DD], s_ssq[DD];
    const int tid = threadIdx.x, wid = tid >> 5, lid = tid & 31;
    const int rg = wid >> 1, ch = wid & 1;
    const long long e0 = (long long)blockIdx.x * DD;

    load_A(e, e0, E, Ahi, Alo, tid, 0, 0);
    if (tid < DD) {
        const long long row = e0 + tid;
        s_src[tid] = (row < E) ? src[row] : 0;
        s_dst[tid] = (row < E) ? dst[row] : 0;
        s_sum[tid] = 0.f;
        s_ssq[tid] = 0.f;
    }
    __syncthreads();

    float acc[2][8][4];
    gemm_core(smem_u32(Ahi), smem_u32(Alo), 0, rg, ch, lid, acc);
    __syncthreads();  // A reads done; reuse smem as fp32 buffer

#pragma unroll
    for (int rb = 0; rb < 2; ++rb) {
        const int r = rg * 32 + rb * 16 + (lid >> 2);
#pragma unroll
        for (int nt = 0; nt < 8; ++nt) {
            const int col = ch * 64 + nt * 8 + (lid & 3) * 2;
            *(float2*)&Bu[r * BUPITCH + col] = make_float2(acc[rb][nt][0], acc[rb][nt][1]);
            *(float2*)&Bu[(r + 8) * BUPITCH + col] = make_float2(acc[rb][nt][2], acc[rb][nt][3]);
        }
    }
    __syncthreads();

    // row epilogue: thread = (col-group cg of 8 cols, row-group rw of 8 rows)
    const int cg = tid & 15, rw = tid >> 4;
    const int c8 = cg * 8;
    float lsum[8], lssq[8];
#pragma unroll
    for (int j = 0; j < 8; ++j) { lsum[j] = 0.f; lssq[j] = 0.f; }
#pragma unroll 2
    for (int i = 0; i < 8; ++i) {
        const int rr = rw * 8 + i;
        const long long row = e0 + rr;
        if (row < E) {
            const int s = s_src[rr], d = s_dst[rr];
            const float4 p0 = *(const float4*)&Bu[rr * BUPITCH + c8];
            const float4 p1 = *(const float4*)&Bu[rr * BUPITCH + c8 + 4];
            const float* hq = g_Hq + (size_t)s * DD + c8;
            const float* hr = g_Hr + (size_t)d * DD + c8;
            const float* vh = g_Vh + (size_t)d * DD + c8;
            const float4 q0 = *(const float4*)hq, q1 = *(const float4*)(hq + 4);
            const float4 r0 = *(const float4*)hr, r1 = *(const float4*)(hr + 4);
            const float v0 = p0.x + q0.x + r0.x, v1 = p0.y + q0.y + r0.y;
            const float v2 = p0.z + q0.z + r0.z, v3 = p0.w + q0.w + r0.w;
            const float v4 = p1.x + q1.x + r1.x, v5 = p1.y + q1.y + r1.y;
            const float v6 = p1.z + q1.z + r1.z, v7 = p1.w + q1.w + r1.w;
            float* eh = g_ehat + (size_t)row * DD + c8;
            *(float4*)eh       = make_float4(v0, v1, v2, v3);
            *(float4*)(eh + 4) = make_float4(v4, v5, v6, v7);
            const float4 w0 = *(const float4*)vh, w1 = *(const float4*)(vh + 4);
            float* ap = g_agg + (size_t)s * DD + c8;
            red4(ap,     sigm(v0) * w0.x, sigm(v1) * w0.y, sigm(v2) * w0.z, sigm(v3) * w0.w);
            red4(ap + 4, sigm(v4) * w1.x, sigm(v5) * w1.y, sigm(v6) * w1.z, sigm(v7) * w1.w);
            lsum[0] += v0; lssq[0] += v0 * v0;  lsum[1] += v1; lssq[1] += v1 * v1;
            lsum[2] += v2; lssq[2] += v2 * v2;  lsum[3] += v3; lssq[3] += v3 * v3;
            lsum[4] += v4; lssq[4] += v4 * v4;  lsum[5] += v5; lssq[5] += v5 * v5;
            lsum[6] += v6; lssq[6] += v6 * v6;  lsum[7] += v7; lssq[7] += v7 * v7;
        }
    }
#pragma unroll
    for (int j = 0; j < 8; ++j) {
        atomicAdd(&s_sum[c8 + j], lsum[j]);
        atomicAdd(&s_ssq[c8 + j], lssq[j]);
    }
    __syncthreads();
    if (tid < DD) {
        atomicAdd(&g_stats[tid], s_sum[tid]);
        atomicAdd(&g_stats[DD + tid], s_ssq[tid]);
    }
}

// ---- edge MLP: e_new = e + relu(BN(ehat)@W1+b1)@W2 + b2 --------------------
__global__ void __launch_bounds__(256, 2)
k_mlp(const float* __restrict__ e, const float* __restrict__ b1,
      const float* __restrict__ b2, const float* __restrict__ ge,
      const float* __restrict__ be, float* __restrict__ out_e, int E) {
    extern __shared__ char sm[];
    char* Ahi = sm;
    char* Alo = sm + 32768;
    __shared__ float s_sc[DD], s_sh[DD];
    const int tid = threadIdx.x, wid = tid >> 5, lid = tid & 31;
    const int rg = wid >> 1, ch = wid & 1;
    const long long e0 = (long long)blockIdx.x * DD;

    if (tid < DD) {
        const float inv = 1.0f / (float)E;
        const float mean = g_stats[tid] * inv;
        const float var = g_stats[DD + tid] * inv - mean * mean;
        const float sc = ge[tid] * rsqrtf(var + 1e-5f);
        s_sc[tid] = sc;
        s_sh[tid] = be[tid] - mean * sc;
    }
    __syncthreads();
    load_A(g_ehat, e0, E, Ahi, Alo, tid, s_sc, s_sh);
    __syncthreads();
    const u32 aHi = smem_u32(Ahi), aLo = smem_u32(Alo);

    float acc[2][8][4];
    gemm_core(aHi, aLo, 5, rg, ch, lid, acc);
    __syncthreads();  // all A reads done before overwrite

    // hidden = relu(acc + b1) -> back into A smem (bf16 hi/lo, swizzled)
#pragma unroll
    for (int rb = 0; rb < 2; ++rb) {
        const int r = rg * 32 + rb * 16 + (lid >> 2);
#pragma unroll
        for (int nt = 0; nt < 8; ++nt) {
            const int col = ch * 64 + nt * 8 + (lid & 3) * 2;
            const float2 bb = *(const float2*)(b1 + col);
            const float v0 = fmaxf(acc[rb][nt][0] + bb.x, 0.f);
            const float v1 = fmaxf(acc[rb][nt][1] + bb.y, 0.f);
            const float v2 = fmaxf(acc[rb][nt][2] + bb.x, 0.f);
            const float v3 = fmaxf(acc[rb][nt][3] + bb.y, 0.f);
            __nv_bfloat162 h0 = __floats2bfloat162_rn(v0, v1);
            __nv_bfloat162 l0 = __floats2bfloat162_rn(v0 - __bfloat162float(h0.x),
                                                      v1 - __bfloat162float(h0.y));
            __nv_bfloat162 h1 = __floats2bfloat162_rn(v2, v3);
            __nv_bfloat162 l1 = __floats2bfloat162_rn(v2 - __bfloat162float(h1.x),
                                                      v3 - __bfloat162float(h1.y));
            const int o0 = swoff(r, col), o1 = swoff(r + 8, col);
            *(u32*)(Ahi + o0) = *(u32*)&h0;
            *(u32*)(Alo + o0) = *(u32*)&l0;
            *(u32*)(Ahi + o1) = *(u32*)&h1;
            *(u32*)(Alo + o1) = *(u32*)&l1;
        }
    }
    __syncthreads();

    gemm_core(aHi, aLo, 6, rg, ch, lid, acc);

#pragma unroll
    for (int rb = 0; rb < 2; ++rb) {
        const long long r0 = e0 + rg * 32 + rb * 16 + (lid >> 2);
        const long long r1 = r0 + 8;
#pragma unroll
        for (int nt = 0; nt < 8; ++nt) {
            const int col = ch * 64 + nt * 8 + (lid & 3) * 2;
            const float2 bb = *(const float2*)(b2 + col);
            if (r0 < E) {
                const float2 ev = *(const float2*)(e + (size_t)r0 * DD + col);
                *(float2*)(out_e + (size_t)r0 * DD + col) =
                    make_float2(acc[rb][nt][0] + bb.x + ev.x, acc[rb][nt][1] + bb.y + ev.y);
            }
            if (r1 < E) {
                const float2 ev = *(const float2*)(e + (size_t)r1 * DD + col);
                *(float2*)(out_e + (size_t)r1 * DD + col) =
                    make_float2(acc[rb][nt][2] + bb.x + ev.x, acc[rb][nt][3] + bb.y + ev.y);
            }
        }
    }
}

// ---------------- node BN stats over x = Hu + agg ----------------
__global__ void k_nstats(int N) {
    const int tid = threadIdx.x;
    const int c = tid & 127, hh = tid >> 7;
    const int rbase = blockIdx.x * DD + hh * 64;
    float s = 0.f, q = 0.f;
    for (int i = 0; i < 64; ++i) {
        const int r = rbase + i;
        if (r < N) {
            const float x = g_Hu[(size_t)r * DD + c] + g_agg[(size_t)r * DD + c];
            s += x;
            q += x * x;
        }
    }
    atomicAdd(&g_stats[2 * DD + c], s);
    atomicAdd(&g_stats[3 * DD + c], q);
}

// ---------------- node finalize ----------------
__global__ void k_nfinal(const float* __restrict__ h, const float* __restrict__ gn,
                         const float* __restrict__ bnb, const float* __restrict__ alpha,
                         float* __restrict__ out, int N) {
    const size_t i = (size_t)blockIdx.x * blockDim.x + threadIdx.x;
    const size_t total = (size_t)N * (DD / 4);
    if (i >= total) return;
    const int c4 = (int)(i & 31);
    const float inv = 1.0f / (float)N;
    const float4 sum = ((const float4*)(g_stats + 2 * DD))[c4];
    const float4 ssq = ((const float4*)(g_stats + 3 * DD))[c4];
    const float4 gnv = ((const float4*)gn)[c4];
    const float4 bnv = ((const float4*)bnb)[c4];
    const float m0 = sum.x * inv, m1 = sum.y * inv, m2 = sum.z * inv, m3 = sum.w * inv;
    const float sc0 = gnv.x * rsqrtf(ssq.x * inv - m0 * m0 + 1e-5f);
    const float sc1 = gnv.y * rsqrtf(ssq.y * inv - m1 * m1 + 1e-5f);
    const float sc2 = gnv.z * rsqrtf(ssq.z * inv - m2 * m2 + 1e-5f);
    const float sc3 = gnv.w * rsqrtf(ssq.w * inv - m3 * m3 + 1e-5f);
    const float sh0 = bnv.x - m0 * sc0, sh1 = bnv.y - m1 * sc1;
    const float sh2 = bnv.z - m2 * sc2, sh3 = bnv.w - m3 * sc3;
    const float4 xu = ((const float4*)g_Hu)[i];
    const float4 ag = ((const float4*)g_agg)[i];
    const float4 hv = ((const float4*)h)[i];
    const float a = *alpha;
    float4 o;
    o.x = hv.x + a * fmaf(xu.x + ag.x, sc0, sh0);
    o.y = hv.y + a * fmaf(xu.y + ag.y, sc1, sh1);
    o.z = hv.z + a * fmaf(xu.z + ag.z, sc2, sh2);
    o.w = hv.w + a * fmaf(xu.w + ag.w, sc3, sh3);
    ((float4*)out)[i] = o;
}

extern "C" void kernel_launch(void* const* d_in, const int* in_sizes, int n_in,
                              void* d_out, int out_size) {
    const float* h   = (const float*)d_in[0];
    const float* e   = (const float*)d_in[1];
    const int*   ei  = (const int*)d_in[2];
    const float* Pw  = (const float*)d_in[3];
    const float* Qw  = (const float*)d_in[4];
    const float* Rw  = (const float*)d_in[5];
    const float* Uw  = (const float*)d_in[6];
    const float* Vw  = (const float*)d_in[7];
    const float* W1  = (const float*)d_in[8];
    const float* b1  = (const float*)d_in[9];
    const float* W2  = (const float*)d_in[10];
    const float* b2  = (const float*)d_in[11];
    const float* ge  = (const float*)d_in[12];
    const float* be  = (const float*)d_in[13];
    const float* gn  = (const float*)d_in[14];
    const float* bnb = (const float*)d_in[15];
    const float* alpha = (const float*)d_in[16];

    const int N = in_sizes[0] / DD;
    const int E = in_sizes[1] / DD;
    const int* src = ei;
    const int* dst = ei + E;

    float* out_h = (float*)d_out;
    float* out_e = out_h + (size_t)N * DD;

    const int SM_AB = 65536;                 // A hi/lo
    const int SM_EH = 128 * BUPITCH * 4;     // 67584: fp32 epilogue buffer
    cudaFuncSetAttribute(k_node, cudaFuncAttributeMaxDynamicSharedMemorySize, SM_AB);
    cudaFuncSetAttribute(k_ehat, cudaFuncAttributeMaxDynamicSharedMemorySize, SM_EH);
    cudaFuncSetAttribute(k_mlp,  cudaFuncAttributeMaxDynamicSharedMemorySize, SM_AB);

    void* agg_ptr;
    cudaGetSymbolAddress(&agg_ptr, g_agg);
    cudaMemsetAsync(agg_ptr, 0, (size_t)N * DD * sizeof(float), 0);

    const int nb  = (N + DD - 1) / DD;
    const int ebt = (E + DD - 1) / DD;

    // launches: memset(1) prep(2) nodeQR(3) nodeVU(4) ehat(5)<-profiled mlp(6) ...
    k_prep<<<7, 256>>>(Pw, Qw, Rw, Vw, Uw, W1, W2);
    k_node<<<nb, 256, SM_AB>>>(h, N, 1);   // Q, R
    k_node<<<nb, 256, SM_AB>>>(h, N, 3);   // V, U
    k_ehat<<<ebt, 256, SM_EH>>>(e, src, dst, E);
    k_mlp<<<ebt, 256, SM_AB>>>(e, b1, b2, ge, be, out_e, E);
    k_nstats<<<nb, 256>>>(N);
    k_nfinal<<<(int)(((size_t)N * 32 + 255) / 256), 256>>>(h, gn, bnb, alpha, out_h, N);
}

// round 7
// speedup vs baseline: 2.8101x; 1.9057x over previous
#include <cuda_runtime.h>
#include <cuda_bf16.h>
#include <cstdint>

#define DD 128
#define NMAX 50000
#define EMAX 640000
#define BUPITCH 132
typedef uint32_t u32;

// ---------------- device scratch ----------------
__device__ __align__(16) float g_Hq[NMAX * DD];
__device__ __align__(16) float g_Hr[NMAX * DD];
__device__ __align__(16) float g_Vh[NMAX * DD];
__device__ __align__(16) float g_Hu[NMAX * DD];
__device__ __align__(16) float g_agg[NMAX * DD];
__device__ __align__(16) float g_ehat[(size_t)EMAX * DD];
__device__ __align__(16) float g_stats[4 * DD];
// B fragments, warp-contiguous blocks: uint4 idx = w*4096 + p*2048 + (ks*8+chunk)*32 + lane
__device__ __align__(16) u32 g_wf[7 * 2 * 8 * 32 * 32];

// ---------------- helpers ----------------
__device__ __forceinline__ u32 smem_u32(const void* p) {
    u32 a;
    asm("{ .reg .u64 t; cvta.to.shared.u64 t, %1; cvt.u32.u64 %0, t; }" : "=r"(a) : "l"(p));
    return a;
}
__device__ __forceinline__ int swoff(int row, int col) {  // bf16 tile 128x128, 256B rows
    return (row << 8) + ((((col >> 3) ^ (row & 7)) << 4)) + ((col & 7) << 1);
}
__device__ __forceinline__ void ldsm4(u32 r[4], u32 a) {
    asm volatile("ldmatrix.sync.aligned.m8n8.x4.shared.b16 {%0,%1,%2,%3}, [%4];"
                 : "=r"(r[0]), "=r"(r[1]), "=r"(r[2]), "=r"(r[3]) : "r"(a));
}
__device__ __forceinline__ void mma_bf16(float c[4], const u32 a[4], u32 b0, u32 b1) {
    asm volatile(
        "mma.sync.aligned.m16n8k16.row.col.f32.bf16.bf16.f32 "
        "{%0,%1,%2,%3},{%4,%5,%6,%7},{%8,%9},{%0,%1,%2,%3};"
        : "+f"(c[0]), "+f"(c[1]), "+f"(c[2]), "+f"(c[3])
        : "r"(a[0]), "r"(a[1]), "r"(a[2]), "r"(a[3]), "r"(b0), "r"(b1));
}
__device__ __forceinline__ float sigm(float x) { return 1.0f / (1.0f + __expf(-x)); }
__device__ __forceinline__ void red4(float* p, float a, float b, float c, float d) {
    asm volatile("red.global.add.v4.f32 [%0], {%1,%2,%3,%4};"
                 :: "l"(p), "f"(a), "f"(b), "f"(c), "f"(d) : "memory");
}

// GEMM core: CTA 128x128, warp tile 32x64 (rg=wid>>1, ch=wid&1).
// A: bf16 hi/lo smem (swizzled); B: coalesced fragment blocks from g_wf.
// 3-pass split AhBh + AhBl + AlBh, fp32 accum.
__device__ __forceinline__ void gemm_core(u32 aHi, u32 aLo, int w, int rg, int ch,
                                          int lid, float acc[2][8][4]) {
#pragma unroll
    for (int rb = 0; rb < 2; ++rb)
#pragma unroll
        for (int nt = 0; nt < 8; ++nt) {
            acc[rb][nt][0] = 0.f; acc[rb][nt][1] = 0.f;
            acc[rb][nt][2] = 0.f; acc[rb][nt][3] = 0.f;
        }
    const int ar0 = rg * 32 + (lid & 7) + ((lid >> 3) & 1) * 8;
    const int kc1 = (lid >> 4) & 1;
    const uint4* wf4 = (const uint4*)g_wf;
    const u32 wbase = (u32)w * 4096u + (u32)(ch * 4) * 32u + (u32)lid;
#pragma unroll
    for (int ks = 0; ks < 8; ++ks) {
        const int akc = 2 * ks + kc1;
        const u32 ao0 = (u32)((ar0 << 8) + ((akc ^ (ar0 & 7)) << 4));
        const int ar1 = ar0 + 16;
        const u32 ao1 = (u32)((ar1 << 8) + ((akc ^ (ar1 & 7)) << 4));
        u32 ah[2][4], al[2][4];
        ldsm4(ah[0], aHi + ao0);
        ldsm4(ah[1], aHi + ao1);
        ldsm4(al[0], aLo + ao0);
        ldsm4(al[1], aLo + ao1);
        const u32 kb = wbase + (u32)(ks * 8) * 32u;
#pragma unroll
        for (int cc = 0; cc < 4; ++cc) {
            const uint4 hh = wf4[kb + (u32)(cc * 32)];
            const uint4 lv = wf4[kb + (u32)(cc * 32) + 2048u];
            const int nt0 = cc * 2, nt1 = cc * 2 + 1;
#pragma unroll
            for (int rb = 0; rb < 2; ++rb) {
                mma_bf16(acc[rb][nt0], ah[rb], hh.x, hh.y);
                mma_bf16(acc[rb][nt0], ah[rb], lv.x, lv.y);
                mma_bf16(acc[rb][nt0], al[rb], hh.x, hh.y);
                mma_bf16(acc[rb][nt1], ah[rb], hh.z, hh.w);
                mma_bf16(acc[rb][nt1], ah[rb], lv.z, lv.w);
                mma_bf16(acc[rb][nt1], al[rb], hh.z, hh.w);
            }
        }
    }
}

// coalesced load: warp lanes cover one row; thread owns 4 cols (col = (tid&31)*4)
__device__ __forceinline__ void load_A(const float* __restrict__ src, long long r0,
                                       long long nrows, char* Ahi, char* Alo, int tid,
                                       const float* sc, const float* sh) {
    const int col = (tid & 31) * 4;
    const int wrow = tid >> 5;
    float4 scv = make_float4(0, 0, 0, 0), shv = scv;
    if (sc) { scv = *(const float4*)(sc + col); shv = *(const float4*)(sh + col); }
#pragma unroll 4
    for (int it = 0; it < 16; ++it) {
        const int row = it * 8 + wrow;
        const long long grow = r0 + row;
        float4 v = make_float4(0.f, 0.f, 0.f, 0.f);
        if (grow < nrows) v = *(const float4*)(src + grow * DD + col);
        if (sc) {
            v.x = fmaf(v.x, scv.x, shv.x);
            v.y = fmaf(v.y, scv.y, shv.y);
            v.z = fmaf(v.z, scv.z, shv.z);
            v.w = fmaf(v.w, scv.w, shv.w);
        }
        __nv_bfloat162 h0 = __floats2bfloat162_rn(v.x, v.y);
        __nv_bfloat162 h1 = __floats2bfloat162_rn(v.z, v.w);
        __nv_bfloat162 l0 = __floats2bfloat162_rn(v.x - __bfloat162float(h0.x),
                                                  v.y - __bfloat162float(h0.y));
        __nv_bfloat162 l1 = __floats2bfloat162_rn(v.z - __bfloat162float(h1.x),
                                                  v.w - __bfloat162float(h1.y));
        const int o = swoff(row, col);
        *(uint2*)(Ahi + o) = make_uint2(*(u32*)&h0, *(u32*)&h1);
        *(uint2*)(Alo + o) = make_uint2(*(u32*)&l0, *(u32*)&l1);
    }
}

// ---------------- prep: weights -> coalesced fragment blocks ----------------
__global__ void k_prep(const float* __restrict__ P, const float* __restrict__ Q,
                       const float* __restrict__ R, const float* __restrict__ V,
                       const float* __restrict__ U, const float* __restrict__ W1,
                       const float* __restrict__ W2) {
    const int w = blockIdx.x;
    const int tid = threadIdx.x;
    const float* Ws[7] = {P, Q, R, V, U, W1, W2};
    const float* W = Ws[w];
    if (w == 0) { g_stats[tid] = 0.f; g_stats[tid + 256] = 0.f; }
    for (int idx = tid; idx < 8192; idx += 256) {
        const int i = idx & 3;
        const int lane = (idx >> 2) & 31;
        const int chunk = (idx >> 7) & 7;
        const int ks = idx >> 10;
        const int j = (chunk >> 2) * 8 + (chunk & 3) * 2 + (i >> 1);
        const int r = i & 1;
        const int n = j * 8 + (lane >> 2);
        const int k = ks * 16 + (lane & 3) * 2 + r * 8;
        const float x0 = W[k * DD + n];
        const float x1 = W[(k + 1) * DD + n];
        __nv_bfloat162 hh = __floats2bfloat162_rn(x0, x1);
        __nv_bfloat162 ll = __floats2bfloat162_rn(x0 - __bfloat162float(hh.x),
                                                  x1 - __bfloat162float(hh.y));
        g_wf[w * 16384 + idx] = *(u32*)&hh;
        g_wf[w * 16384 + 8192 + idx] = *(u32*)&ll;
    }
}

// ---------------- node GEMMs: two weights per launch ------------------------
__global__ void __launch_bounds__(256, 2)
k_node(const float* __restrict__ h, int N, int w0) {
    extern __shared__ char sm[];
    char* Ahi = sm;
    char* Alo = sm + 32768;
    const int tid = threadIdx.x, wid = tid >> 5, lid = tid & 31;
    const int rg = wid >> 1, ch = wid & 1;
    const long long n0 = (long long)blockIdx.x * DD;

    load_A(h, n0, N, Ahi, Alo, tid, 0, 0);
    __syncthreads();
    const u32 aHi = smem_u32(Ahi), aLo = smem_u32(Alo);

    float* Outs[5] = {0, g_Hq, g_Hr, g_Vh, g_Hu};
#pragma unroll 1
    for (int w = w0; w < w0 + 2; ++w) {
        float acc[2][8][4];
        gemm_core(aHi, aLo, w, rg, ch, lid, acc);
        float* Out = Outs[w];
#pragma unroll
        for (int rb = 0; rb < 2; ++rb) {
            const long long r0 = n0 + rg * 32 + rb * 16 + (lid >> 2);
            const long long r1 = r0 + 8;
#pragma unroll
            for (int nt = 0; nt < 8; ++nt) {
                const int col = ch * 64 + nt * 8 + (lid & 3) * 2;
                if (r0 < N) *(float2*)(Out + (size_t)r0 * DD + col) =
                    make_float2(acc[rb][nt][0], acc[rb][nt][1]);
                if (r1 < N) *(float2*)(Out + (size_t)r1 * DD + col) =
                    make_float2(acc[rb][nt][2], acc[rb][nt][3]);
            }
        }
    }
}

// write warp fragments into fp32 smem buffer (pitch BUPITCH)
__device__ __forceinline__ void frag_to_bu(float* Bu, const float acc[2][8][4],
                                           int rg, int ch, int lid) {
#pragma unroll
    for (int rb = 0; rb < 2; ++rb) {
        const int r = rg * 32 + rb * 16 + (lid >> 2);
#pragma unroll
        for (int nt = 0; nt < 8; ++nt) {
            const int col = ch * 64 + nt * 8 + (lid & 3) * 2;
            *(float2*)&Bu[r * BUPITCH + col] = make_float2(acc[rb][nt][0], acc[rb][nt][1]);
            *(float2*)&Bu[(r + 8) * BUPITCH + col] = make_float2(acc[rb][nt][2], acc[rb][nt][3]);
        }
    }
}

// ---- edge: ehat = e@P + Hq[src]+Hr[dst]; gate scatter; BN-e stats ----------
__global__ void __launch_bounds__(256, 2)
k_ehat(const float* __restrict__ e, const int* __restrict__ src,
       const int* __restrict__ dst, int E) {
    extern __shared__ char sm[];
    char* Ahi = sm;
    char* Alo = sm + 32768;
    float* Bu = (float*)sm;  // fp32 128x132, overlays A after GEMM
    __shared__ int s_src[DD], s_dst[DD];
    __shared__ float s_sum[DD], s_ssq[DD];
    const int tid = threadIdx.x, wid = tid >> 5, lid = tid & 31;
    const int rg = wid >> 1, ch = wid & 1;
    const long long e0 = (long long)blockIdx.x * DD;

    load_A(e, e0, E, Ahi, Alo, tid, 0, 0);
    if (tid < DD) {
        const long long row = e0 + tid;
        s_src[tid] = (row < E) ? src[row] : 0;
        s_dst[tid] = (row < E) ? dst[row] : 0;
        s_sum[tid] = 0.f;
        s_ssq[tid] = 0.f;
    }
    __syncthreads();

    float acc[2][8][4];
    gemm_core(smem_u32(Ahi), smem_u32(Alo), 0, rg, ch, lid, acc);
    __syncthreads();
    frag_to_bu(Bu, acc, rg, ch, lid);
    __syncthreads();

    // coalesced epilogue: thread owns 4 fixed cols, walks 16 rows
    const int col = (tid & 31) * 4;
    const int wrow = tid >> 5;
    float ls0 = 0.f, ls1 = 0.f, ls2 = 0.f, ls3 = 0.f;
    float lq0 = 0.f, lq1 = 0.f, lq2 = 0.f, lq3 = 0.f;
#pragma unroll 2
    for (int it = 0; it < 16; ++it) {
        const int rr = it * 8 + wrow;
        const long long row = e0 + rr;
        if (row < E) {
            const int s = s_src[rr], d = s_dst[rr];
            const float4 p = *(const float4*)&Bu[rr * BUPITCH + col];
            const float4 q = *(const float4*)(g_Hq + (size_t)s * DD + col);
            const float4 rv = *(const float4*)(g_Hr + (size_t)d * DD + col);
            const float4 wv = *(const float4*)(g_Vh + (size_t)d * DD + col);
            const float v0 = p.x + q.x + rv.x;
            const float v1 = p.y + q.y + rv.y;
            const float v2 = p.z + q.z + rv.z;
            const float v3 = p.w + q.w + rv.w;
            *(float4*)(g_ehat + (size_t)row * DD + col) = make_float4(v0, v1, v2, v3);
            red4(g_agg + (size_t)s * DD + col,
                 sigm(v0) * wv.x, sigm(v1) * wv.y, sigm(v2) * wv.z, sigm(v3) * wv.w);
            ls0 += v0; lq0 += v0 * v0;
            ls1 += v1; lq1 += v1 * v1;
            ls2 += v2; lq2 += v2 * v2;
            ls3 += v3; lq3 += v3 * v3;
        }
    }
    atomicAdd(&s_sum[col], ls0);     atomicAdd(&s_ssq[col], lq0);
    atomicAdd(&s_sum[col + 1], ls1); atomicAdd(&s_ssq[col + 1], lq1);
    atomicAdd(&s_sum[col + 2], ls2); atomicAdd(&s_ssq[col + 2], lq2);
    atomicAdd(&s_sum[col + 3], ls3); atomicAdd(&s_ssq[col + 3], lq3);
    __syncthreads();
    if (tid < DD) {
        atomicAdd(&g_stats[tid], s_sum[tid]);
        atomicAdd(&g_stats[DD + tid], s_ssq[tid]);
    }
}

// ---- edge MLP: e_new = e + relu(BN(ehat)@W1+b1)@W2 + b2 --------------------
__global__ void __launch_bounds__(256, 2)
k_mlp(const float* __restrict__ e, const float* __restrict__ b1,
      const float* __restrict__ b2, const float* __restrict__ ge,
      const float* __restrict__ be, float* __restrict__ out_e, int E) {
    extern __shared__ char sm[];
    char* Ahi = sm;
    char* Alo = sm + 32768;
    float* Bu = (float*)sm;
    __shared__ float s_sc[DD], s_sh[DD];
    const int tid = threadIdx.x, wid = tid >> 5, lid = tid & 31;
    const int rg = wid >> 1, ch = wid & 1;
    const long long e0 = (long long)blockIdx.x * DD;

    if (tid < DD) {
        const float inv = 1.0f / (float)E;
        const float mean = g_stats[tid] * inv;
        const float var = g_stats[DD + tid] * inv - mean * mean;
        const float sc = ge[tid] * rsqrtf(var + 1e-5f);
        s_sc[tid] = sc;
        s_sh[tid] = be[tid] - mean * sc;
    }
    __syncthreads();
    load_A(g_ehat, e0, E, Ahi, Alo, tid, s_sc, s_sh);
    __syncthreads();
    const u32 aHi = smem_u32(Ahi), aLo = smem_u32(Alo);

    float acc[2][8][4];
    gemm_core(aHi, aLo, 5, rg, ch, lid, acc);
    __syncthreads();  // all GEMM1 A reads done

    // hidden = relu(acc + b1) -> back into A smem (bf16 hi/lo, swizzled)
#pragma unroll
    for (int rb = 0; rb < 2; ++rb) {
        const int r = rg * 32 + rb * 16 + (lid >> 2);
#pragma unroll
        for (int nt = 0; nt < 8; ++nt) {
            const int col = ch * 64 + nt * 8 + (lid & 3) * 2;
            const float2 bb = *(const float2*)(b1 + col);
            const float v0 = fmaxf(acc[rb][nt][0] + bb.x, 0.f);
            const float v1 = fmaxf(acc[rb][nt][1] + bb.y, 0.f);
            const float v2 = fmaxf(acc[rb][nt][2] + bb.x, 0.f);
            const float v3 = fmaxf(acc[rb][nt][3] + bb.y, 0.f);
            __nv_bfloat162 h0 = __floats2bfloat162_rn(v0, v1);
            __nv_bfloat162 l0 = __floats2bfloat162_rn(v0 - __bfloat162float(h0.x),
                                                      v1 - __bfloat162float(h0.y));
            __nv_bfloat162 h1 = __floats2bfloat162_rn(v2, v3);
            __nv_bfloat162 l1 = __floats2bfloat162_rn(v2 - __bfloat162float(h1.x),
                                                      v3 - __bfloat162float(h1.y));
            const int o0 = swoff(r, col), o1 = swoff(r + 8, col);
            *(u32*)(Ahi + o0) = *(u32*)&h0;
            *(u32*)(Alo + o0) = *(u32*)&l0;
            *(u32*)(Ahi + o1) = *(u32*)&h1;
            *(u32*)(Alo + o1) = *(u32*)&l1;
        }
    }
    __syncthreads();

    gemm_core(aHi, aLo, 6, rg, ch, lid, acc);
    __syncthreads();  // GEMM2 A reads done; Bu overlays A
    frag_to_bu(Bu, acc, rg, ch, lid);
    __syncthreads();

    // coalesced output epilogue
    const int col = (tid & 31) * 4;
    const int wrow = tid >> 5;
    const float4 bb = *(const float4*)(b2 + col);
#pragma unroll 2
    for (int it = 0; it < 16; ++it) {
        const int rr = it * 8 + wrow;
        const long long row = e0 + rr;
        if (row < E) {
            const float4 p = *(const float4*)&Bu[rr * BUPITCH + col];
            const float4 ev = *(const float4*)(e + (size_t)row * DD + col);
            *(float4*)(out_e + (size_t)row * DD + col) = make_float4(
                p.x + bb.x + ev.x, p.y + bb.y + ev.y,
                p.z + bb.z + ev.z, p.w + bb.w + ev.w);
        }
    }
}

// ---------------- node BN stats over x = Hu + agg ----------------
__global__ void k_nstats(int N) {
    const int tid = threadIdx.x;
    const int c = tid & 127, hh = tid >> 7;
    const int rbase = blockIdx.x * DD + hh * 64;
    float s = 0.f, q = 0.f;
    for (int i = 0; i < 64; ++i) {
        const int r = rbase + i;
        if (r < N) {
            const float x = g_Hu[(size_t)r * DD + c] + g_agg[(size_t)r * DD + c];
            s += x;
            q += x * x;
        }
    }
    atomicAdd(&g_stats[2 * DD + c], s);
    atomicAdd(&g_stats[3 * DD + c], q);
}

// ---------------- node finalize ----------------
__global__ void k_nfinal(const float* __restrict__ h, const float* __restrict__ gn,
                         const float* __restrict__ bnb, const float* __restrict__ alpha,
                         float* __restrict__ out, int N) {
    const size_t i = (size_t)blockIdx.x * blockDim.x + threadIdx.x;
    const size_t total = (size_t)N * (DD / 4);
    if (i >= total) return;
    const int c4 = (int)(i & 31);
    const float inv = 1.0f / (float)N;
    const float4 sum = ((const float4*)(g_stats + 2 * DD))[c4];
    const float4 ssq = ((const float4*)(g_stats + 3 * DD))[c4];
    const float4 gnv = ((const float4*)gn)[c4];
    const float4 bnv = ((const float4*)bnb)[c4];
    const float m0 = sum.x * inv, m1 = sum.y * inv, m2 = sum.z * inv, m3 = sum.w * inv;
    const float sc0 = gnv.x * rsqrtf(ssq.x * inv - m0 * m0 + 1e-5f);
    const float sc1 = gnv.y * rsqrtf(ssq.y * inv - m1 * m1 + 1e-5f);
    const float sc2 = gnv.z * rsqrtf(ssq.z * inv - m2 * m2 + 1e-5f);
    const float sc3 = gnv.w * rsqrtf(ssq.w * inv - m3 * m3 + 1e-5f);
    const float sh0 = bnv.x - m0 * sc0, sh1 = bnv.y - m1 * sc1;
    const float sh2 = bnv.z - m2 * sc2, sh3 = bnv.w - m3 * sc3;
    const float4 xu = ((const float4*)g_Hu)[i];
    const float4 ag = ((const float4*)g_agg)[i];
    const float4 hv = ((const float4*)h)[i];
    const float a = *alpha;
    float4 o;
    o.x = hv.x + a * fmaf(xu.x + ag.x, sc0, sh0);
    o.y = hv.y + a * fmaf(xu.y + ag.y, sc1, sh1);
    o.z = hv.z + a * fmaf(xu.z + ag.z, sc2, sh2);
    o.w = hv.w + a * fmaf(xu.w + ag.w, sc3, sh3);
    ((float4*)out)[i] = o;
}

extern "C" void kernel_launch(void* const* d_in, const int* in_sizes, int n_in,
                              void* d_out, int out_size) {
    const float* h   = (const float*)d_in[0];
    const float* e   = (const float*)d_in[1];
    const int*   ei  = (const int*)d_in[2];
    const float* Pw  = (const float*)d_in[3];
    const float* Qw  = (const float*)d_in[4];
    const float* Rw  = (const float*)d_in[5];
    const float* Uw  = (const float*)d_in[6];
    const float* Vw  = (const float*)d_in[7];
    const float* W1  = (const float*)d_in[8];
    const float* b1  = (const float*)d_in[9];
    const float* W2  = (const float*)d_in[10];
    const float* b2  = (const float*)d_in[11];
    const float* ge  = (const float*)d_in[12];
    const float* be  = (const float*)d_in[13];
    const float* gn  = (const float*)d_in[14];
    const float* bnb = (const float*)d_in[15];
    const float* alpha = (const float*)d_in[16];

    const int N = in_sizes[0] / DD;
    const int E = in_sizes[1] / DD;
    const int* src = ei;
    const int* dst = ei + E;

    float* out_h = (float*)d_out;
    float* out_e = out_h + (size_t)N * DD;

    const int SM_AB = 65536;              // A hi/lo
    const int SM_BU = 128 * BUPITCH * 4;  // 67584: fp32 epilogue buffer (overlays A)
    cudaFuncSetAttribute(k_node, cudaFuncAttributeMaxDynamicSharedMemorySize, SM_AB);
    cudaFuncSetAttribute(k_ehat, cudaFuncAttributeMaxDynamicSharedMemorySize, SM_BU);
    cudaFuncSetAttribute(k_mlp,  cudaFuncAttributeMaxDynamicSharedMemorySize, SM_BU);

    void* agg_ptr;
    cudaGetSymbolAddress(&agg_ptr, g_agg);
    cudaMemsetAsync(agg_ptr, 0, (size_t)N * DD * sizeof(float), 0);

    const int nb  = (N + DD - 1) / DD;
    const int ebt = (E + DD - 1) / DD;

    // launches: memset(1) prep(2) nodeQR(3) nodeVU(4) ehat(5)<-profiled mlp(6) ...
    k_prep<<<7, 256>>>(Pw, Qw, Rw, Vw, Uw, W1, W2);
    k_node<<<nb, 256, SM_AB>>>(h, N, 1);   // Q, R
    k_node<<<nb, 256, SM_AB>>>(h, N, 3);   // V, U
    k_ehat<<<ebt, 256, SM_BU>>>(e, src, dst, E);
    k_mlp<<<ebt, 256, SM_BU>>>(e, b1, b2, ge, be, out_e, E);
    k_nstats<<<nb, 256>>>(N);
    k_nfinal<<<(int)(((size_t)N * 32 + 255) / 256), 256>>>(h, gn, bnb, alpha, out_h, N);
}